// round 14
// baseline (speedup 1.0000x reference)
#include <cuda_runtime.h>
#include <cuda_fp16.h>
#include <cstdint>

// ============================================================================
// INT4Linear on GB300 — persistent tcgen05 cg1, 256x256 tile + supertile order.
//   out[M,N] = x[M,K] @ W[N,K]^T + bias     M=8192 N=4096 K=4096
// R13: 128x256 supertile hit 65.6% tensor == SMEM-port model's 67% prediction
// (187 B/cyc demand vs 128). 256x256 drops demand to 125 B/cyc (<= port):
// A 32KB + B 32KB per K-chunk per 1024 tensor cycles. R9 proved this tile's
// MMA/epilogue correct; R13 proved the L2 supertile order. This = both.
// k1: fused prepass (R10-proven). k2: persistent GEMM, 3-stage 64KB pipeline,
// single-buffered TMEM (512 cols = 2 x M128xN256 fp32 accumulators).
// ============================================================================

#if defined(__CUDA_ARCH_FEAT_SM103_ALL) || defined(__CUDA_ARCH_FEAT_SM100_ALL)
#define TC_PATH 1
#else
#define TC_PATH 0
#endif

#define KC_ELEMS 64
#define BLK_BYTES 16384
#define STAGES 3
#define STAGE_BYTES (4 * BLK_BYTES)   // A 32KB (2 blocks) + B 32KB (2 blocks)
#define SMEM_STAGE0 1024
#define SMEM_TOTAL_GEMM (SMEM_STAGE0 + STAGES * STAGE_BYTES)   // 197632
#define THREADS 320
#define NB_GROUP 8                    // supertile width in nb (256-wide tiles)

__device__ __half g_W[4096u * 4096u];   // 32 MB, [N/256][K/64][2][128x64] SW128
__device__ __half g_X[8192u * 4096u];   // 64 MB, [M/128][K/64][128x64] SW128

__host__ __device__ __forceinline__ uint32_t swz128(uint32_t o) {
    return o ^ ((o >> 3) & 0x70);
}
__device__ __forceinline__ uint32_t smem_u32(const void* p) {
    return (uint32_t)__cvta_generic_to_shared(p);
}
// L2-aware tile order: groups of NB_GROUP nb-columns, mb-major inside a group.
__device__ __forceinline__ void tile_coords(int t, int TILES_M, int& mb, int& nb) {
    const int per_group = TILES_M * NB_GROUP;       // 256
    const int g = t / per_group;
    const int r = t - g * per_group;
    mb = r >> 3;                                     // r / NB_GROUP
    nb = g * NB_GROUP + (r & (NB_GROUP - 1));
}

// ---------------------------------------------------------------------------
#if TC_PATH
__device__ __forceinline__ void mbar_init(uint32_t a, uint32_t cnt) {
    asm volatile("mbarrier.init.shared.b64 [%0], %1;" :: "r"(a), "r"(cnt) : "memory");
}
__device__ __forceinline__ void mbar_arrive(uint32_t a) {
    asm volatile("mbarrier.arrive.shared.b64 _, [%0];" :: "r"(a) : "memory");
}
__device__ __forceinline__ void mbar_expect_tx(uint32_t a, uint32_t bytes) {
    asm volatile("mbarrier.arrive.expect_tx.shared.b64 _, [%0], %1;"
                 :: "r"(a), "r"(bytes) : "memory");
}
__device__ __forceinline__ void mbar_wait(uint32_t a, uint32_t parity) {
    uint32_t done;
    asm volatile(
        "{\n\t.reg .pred p;\n\t"
        "mbarrier.try_wait.parity.acquire.cta.shared::cta.b64 p, [%1], %2;\n\t"
        "selp.b32 %0, 1, 0, p;\n\t}"
        : "=r"(done) : "r"(a), "r"(parity) : "memory");
    if (!done) {
        asm volatile(
            "{\n\t.reg .pred P1;\n\t"
            "W0_%=:\n\t"
            "mbarrier.try_wait.parity.acquire.cta.shared::cta.b64 P1, [%0], %1, 0x989680;\n\t"
            "@P1 bra.uni W1_%=;\n\t"
            "bra.uni W0_%=;\n\t"
            "W1_%=:\n\t}"
            :: "r"(a), "r"(parity) : "memory");
    }
}
__device__ __forceinline__ void bulk_g2s(uint32_t dst, const void* src,
                                         uint32_t bytes, uint32_t mbar) {
    asm volatile(
        "cp.async.bulk.shared::cluster.global.mbarrier::complete_tx::bytes "
        "[%0], [%1], %2, [%3];"
        :: "r"(dst), "l"(src), "r"(bytes), "r"(mbar) : "memory");
}
__device__ __forceinline__ void tmem_alloc(uint32_t smem_slot, uint32_t ncols) {
    asm volatile("tcgen05.alloc.cta_group::1.sync.aligned.shared::cta.b32 [%0], %1;"
                 :: "r"(smem_slot), "r"(ncols) : "memory");
}
__device__ __forceinline__ void tmem_relinquish() {
    asm volatile("tcgen05.relinquish_alloc_permit.cta_group::1.sync.aligned;");
}
__device__ __forceinline__ void tmem_dealloc(uint32_t base, uint32_t ncols) {
    asm volatile("tcgen05.dealloc.cta_group::1.sync.aligned.b32 %0, %1;"
                 :: "r"(base), "r"(ncols));
}
__device__ __forceinline__ void mma_f16_ss(uint32_t d_tmem, uint64_t a_desc,
                                           uint64_t b_desc, uint32_t idesc,
                                           uint32_t enable) {
    asm volatile(
        "{\n\t.reg .pred p;\n\t"
        "setp.ne.u32 p, %5, 0;\n\t"
        "tcgen05.mma.cta_group::1.kind::f16 [%0], %1, %2, %3, {%4, %4, %4, %4}, p;\n\t}"
        :: "r"(d_tmem), "l"(a_desc), "l"(b_desc), "r"(idesc), "r"(0u), "r"(enable)
        : "memory");
}
__device__ __forceinline__ void tc_commit(uint32_t mbar) {
    asm volatile(
        "tcgen05.commit.cta_group::1.mbarrier::arrive::one.shared::cluster.b64 [%0];"
        :: "r"(mbar) : "memory");
}
__device__ __forceinline__ void tc_fence_after() {
    asm volatile("tcgen05.fence::after_thread_sync;" ::: "memory");
}
__device__ __forceinline__ void tc_fence_before() {
    asm volatile("tcgen05.fence::before_thread_sync;" ::: "memory");
}
__device__ __forceinline__ void ldtm_x32(uint32_t* r, uint32_t addr) {
    asm volatile(
        "tcgen05.ld.sync.aligned.32x32b.x32.b32 "
        "{%0,%1,%2,%3,%4,%5,%6,%7,%8,%9,%10,%11,%12,%13,%14,%15,"
        "%16,%17,%18,%19,%20,%21,%22,%23,%24,%25,%26,%27,%28,%29,%30,%31}, [%32];"
        : "=r"(r[0]), "=r"(r[1]), "=r"(r[2]), "=r"(r[3]),
          "=r"(r[4]), "=r"(r[5]), "=r"(r[6]), "=r"(r[7]),
          "=r"(r[8]), "=r"(r[9]), "=r"(r[10]), "=r"(r[11]),
          "=r"(r[12]), "=r"(r[13]), "=r"(r[14]), "=r"(r[15]),
          "=r"(r[16]), "=r"(r[17]), "=r"(r[18]), "=r"(r[19]),
          "=r"(r[20]), "=r"(r[21]), "=r"(r[22]), "=r"(r[23]),
          "=r"(r[24]), "=r"(r[25]), "=r"(r[26]), "=r"(r[27]),
          "=r"(r[28]), "=r"(r[29]), "=r"(r[30]), "=r"(r[31])
        : "r"(addr));
}
__device__ __forceinline__ void tc_wait_ld() {
    asm volatile("tcgen05.wait::ld.sync.aligned;" ::: "memory");
}
// SW128 K-major SMEM descriptor (version=1, LBO=1, SBO=64)
__device__ __forceinline__ uint64_t make_desc(uint32_t smem_addr) {
    const uint64_t base =
        (uint64_t(2) << 61) | (uint64_t(1) << 46) | (uint64_t(64) << 32) | (uint64_t(1) << 16);
    return base | ((uint64_t)(smem_addr >> 4) & 0x3FFF);
}
// idesc cg1: dtype F32 (1<<4), fp16 a/b, N=256 (32<<17), M=128 (8<<24)
#define IDESC 0x8400010u
#endif  // TC_PATH

// ---------------------------------------------------------------------------
// k1: fused prepass (R10-proven). Block bid < wblocks: W block; else X block.
// ---------------------------------------------------------------------------
__global__ __launch_bounds__(256)
void prepass_kernel(const float* __restrict__ x,
                    const int* __restrict__ packed,
                    const float* __restrict__ scale_p,
                    int K, int KC, int wblocks) {
    const int bid = blockIdx.x;
    const int tid = threadIdx.x;

    if (bid < wblocks) {
        const float s = __ldg(scale_p);
        const int K2 = K >> 1;
        const int nkc  = bid >> 1;
        const int half = bid & 1;
        const int n2 = nkc / KC;
        const int kc = nkc - n2 * KC;
        const int nbase = n2 * 256 + half * 128;
        char* outb = reinterpret_cast<char*>(g_W) + (size_t)bid * BLK_BYTES;

#pragma unroll
        for (int it = 0; it < 4; ++it) {
            const int u   = tid + it * 256;
            const int row = u >> 3;
            const int cg  = u & 7;
            const int4 v = *reinterpret_cast<const int4*>(
                packed + (size_t)(nbase + row) * K2 + kc * 32 + cg * 4);
            __half o[8];
            const int b4[4] = {v.x, v.y, v.z, v.w};
#pragma unroll
            for (int j = 0; j < 4; ++j) {
                int hi = b4[j] >> 4;
                int lo = ((b4[j] & 15) ^ 8) - 8;
                o[2 * j]     = __float2half_rn((float)hi * s);
                o[2 * j + 1] = __float2half_rn((float)lo * s);
            }
            *reinterpret_cast<uint4*>(outb + swz128((uint32_t)(row * 128 + cg * 16))) =
                *reinterpret_cast<const uint4*>(o);
        }
    } else {
        const int xb = bid - wblocks;
        const int mb = xb / KC;
        const int kc = xb - mb * KC;
        const float* xin = x + (size_t)(mb * 128) * K + kc * 64;
        char* outb = reinterpret_cast<char*>(g_X) + (size_t)xb * BLK_BYTES;

#pragma unroll
        for (int it = 0; it < 4; ++it) {
            const int u   = tid + it * 256;
            const int row = u >> 3;
            const int cg  = u & 7;
            const float4* src = reinterpret_cast<const float4*>(
                xin + (size_t)row * K + cg * 8);
            const float4 a = src[0];
            const float4 c = src[1];
            __half o[8];
            o[0] = __float2half_rn(a.x); o[1] = __float2half_rn(a.y);
            o[2] = __float2half_rn(a.z); o[3] = __float2half_rn(a.w);
            o[4] = __float2half_rn(c.x); o[5] = __float2half_rn(c.y);
            o[6] = __float2half_rn(c.z); o[7] = __float2half_rn(c.w);
            *reinterpret_cast<uint4*>(outb + swz128((uint32_t)(row * 128 + cg * 16))) =
                *reinterpret_cast<const uint4*>(o);
        }
    }
}

// ---------------------------------------------------------------------------
// k2: persistent GEMM, 256x256 tiles, supertile order. grid = #SMs.
// smem: full[3]@0, empty[3]@24, done@48, efree@56, tslot@64,
//       stages @1024: A0 16KB | A1 16KB | B 32KB.
// ---------------------------------------------------------------------------
__global__ __launch_bounds__(THREADS, 1)
void gemm_kernel(const float* __restrict__ bias,
                 float* __restrict__ Out,
                 int M, int N, int K, int ntiles) {
    extern __shared__ char smem[];
    const uint32_t sbase = smem_u32(smem);
    const int tid  = threadIdx.x;
    const int wid  = tid >> 5;
    const int lane = tid & 31;

    const int KC      = K / KC_ELEMS;            // 64 chunks per tile
    const int TILES_M = M / 256;                 // 32

#if TC_PATH
    const uint32_t full0  = sbase;
    const uint32_t empty0 = sbase + 24;
    const uint32_t doneb  = sbase + 48;
    const uint32_t efree  = sbase + 56;
    const uint32_t tslot  = sbase + 64;

    if (tid == 0) {
#pragma unroll
        for (int s = 0; s < STAGES; ++s) {
            mbar_init(full0 + s * 8, 1);
            mbar_init(empty0 + s * 8, 1);
        }
        mbar_init(doneb, 1);
        mbar_init(efree, 8);                     // 8 epilogue warps
    }
    __syncthreads();

    if (wid == 8) {
        tmem_alloc(tslot, 512);                  // two M-half accumulators
        tmem_relinquish();
    }
    __syncthreads();
    uint32_t tmem_base;
    asm volatile("ld.shared.b32 %0, [%1];" : "=r"(tmem_base) : "r"(tslot));

    // ==================== producer: warp 8, lane 0 ====================
    if (tid == 256) {
        int s = 0, ph = 1;
        for (int t = blockIdx.x; t < ntiles; t += gridDim.x) {
            int mb, nb;
            tile_coords(t, TILES_M, mb, nb);
            const char* A0 = reinterpret_cast<const char*>(g_X) +
                             (size_t)(mb * 2)     * KC * BLK_BYTES;
            const char* A1 = reinterpret_cast<const char*>(g_X) +
                             (size_t)(mb * 2 + 1) * KC * BLK_BYTES;
            const char* Bs = reinterpret_cast<const char*>(g_W) +
                             (size_t)nb * KC * 2 * BLK_BYTES;
            for (int i = 0; i < KC; ++i) {
                mbar_wait(empty0 + s * 8, ph);
                const uint32_t fb = full0 + s * 8;
                mbar_expect_tx(fb, STAGE_BYTES);
                const uint32_t stg = sbase + SMEM_STAGE0 + s * STAGE_BYTES;
                bulk_g2s(stg,                 A0 + (size_t)i * BLK_BYTES,     BLK_BYTES,     fb);
                bulk_g2s(stg + BLK_BYTES,     A1 + (size_t)i * BLK_BYTES,     BLK_BYTES,     fb);
                bulk_g2s(stg + 2 * BLK_BYTES, Bs + (size_t)i * 2 * BLK_BYTES, 2 * BLK_BYTES, fb);
                if (++s == STAGES) { s = 0; ph ^= 1; }
            }
        }
    }

    // ==================== MMA issuer: warp 9, lane 0 ====================
    if (tid == 288) {
        int s = 0, ph = 0;
        int j = 0;
        for (int t = blockIdx.x; t < ntiles; t += gridDim.x, ++j) {
            if (j > 0) mbar_wait(efree, (j - 1) & 1);   // accumulators drained
            tc_fence_after();
            for (int i = 0; i < KC; ++i) {
                mbar_wait(full0 + s * 8, ph);
                const uint32_t stg = sbase + SMEM_STAGE0 + s * STAGE_BYTES;
                uint64_t a0 = make_desc(stg);
                uint64_t a1 = make_desc(stg + BLK_BYTES);
                uint64_t bd = make_desc(stg + 2 * BLK_BYTES);
                const uint32_t en = (i > 0) ? 1u : 0u;
#pragma unroll
                for (int ks = 0; ks < 4; ++ks) {
                    const uint32_t e = (en | (ks > 0)) ? 1u : 0u;
                    mma_f16_ss(tmem_base,       a0 + ks * 2, bd + ks * 2, IDESC, e);
                    mma_f16_ss(tmem_base + 256, a1 + ks * 2, bd + ks * 2, IDESC, e);
                }
                tc_commit(empty0 + s * 8);
                if (++s == STAGES) { s = 0; ph ^= 1; }
            }
            tc_commit(doneb);
        }
    }

    // ==================== epilogue: warps 0-7 (256 rows) ====================
    if (wid < 8) {
        const int mhalf = wid >> 2;              // 0: rows 0-127, 1: 128-255
        const int subp  = wid & 3;               // TMEM subpartition
        int j = 0;
        for (int t = blockIdx.x; t < ntiles; t += gridDim.x, ++j) {
            mbar_wait(doneb, j & 1);
            tc_fence_after();

            int mb, nb;
            tile_coords(t, TILES_M, mb, nb);
            const int row = mb * 256 + mhalf * 128 + subp * 32 + lane;
            float* orow = Out + (size_t)row * N + nb * 256;
            const float* brow = bias + nb * 256;
            const uint32_t tacc = tmem_base + mhalf * 256;

#pragma unroll
            for (int cb = 0; cb < 8; ++cb) {
                uint32_t r32[32];
                ldtm_x32(r32, tacc + cb * 32);
                tc_wait_ld();
                float o[32];
#pragma unroll
                for (int q = 0; q < 8; ++q) {
                    const float4 bf = *reinterpret_cast<const float4*>(brow + cb * 32 + q * 4);
                    const float bfv[4] = {bf.x, bf.y, bf.z, bf.w};
#pragma unroll
                    for (int e = 0; e < 4; ++e) {
                        const int c = q * 4 + e;
                        __half h  = __float2half_rn(__uint_as_float(r32[c]));
                        __half hb = __float2half_rn(bfv[e]);
                        o[c] = __half2float(__hadd(h, hb));
                    }
                }
#pragma unroll
                for (int q = 0; q < 8; ++q) {
                    reinterpret_cast<float4*>(orow + cb * 32)[q] =
                        make_float4(o[4 * q], o[4 * q + 1], o[4 * q + 2], o[4 * q + 3]);
                }
            }
            tc_fence_before();
            if (lane == 0) mbar_arrive(efree);
        }
    }

    __syncthreads();
    if (wid == 8) tmem_dealloc(tmem_base, 512);

#else
    // =============== compile-only fallback (never selected on GB300) =======
    for (int t = blockIdx.x; t < ntiles; t += gridDim.x) {
        int mb, nb;
        tile_coords(t, TILES_M, mb, nb);
        for (int rr = tid; rr < 256; rr += THREADS) {
            const int m = mb * 256 + rr;
            for (int c = 0; c < 256; ++c) {
                const int n = nb * 256 + c;
                float acc = 0.0f;
                for (int k = 0; k < K; ++k) {
                    size_t ablk = (size_t)(m >> 7) * KC + (k >> 6);
                    const __half* ae = reinterpret_cast<const __half*>(
                        reinterpret_cast<const char*>(g_X) + ablk * BLK_BYTES +
                        swz128((uint32_t)((m & 127) * 128 + (k & 63) * 2)));
                    size_t bblk = ((size_t)(n >> 8) * KC + (k >> 6)) * 2 + ((n >> 7) & 1);
                    const __half* be = reinterpret_cast<const __half*>(
                        reinterpret_cast<const char*>(g_W) + bblk * BLK_BYTES +
                        swz128((uint32_t)((n & 127) * 128 + (k & 63) * 2)));
                    acc += __half2float(*ae) * __half2float(*be);
                }
                __half h = __hadd(__float2half_rn(acc), __float2half_rn(bias[n]));
                Out[(size_t)m * N + n] = __half2float(h);
            }
        }
    }
#endif
}

// ---------------------------------------------------------------------------
extern "C" void kernel_launch(void* const* d_in, const int* in_sizes, int n_in,
                              void* d_out, int out_size) {
    const float* x     = (const float*)d_in[0];
    const int*   wq    = (const int*)d_in[1];
    const float* scale = (const float*)d_in[2];
    const float* bias  = (const float*)d_in[3];
    float*       out   = (float*)d_out;

    const int O = in_sizes[3];                    // 4096
    const int K = (in_sizes[1] / O) * 2;          // 4096
    const int M = in_sizes[0] / K;                // 8192
    const int N = O;
    const int KC = K / KC_ELEMS;                  // 64
    const int ntiles = (M / 256) * (N / 256);     // 512

    const int wblocks = (N / 128) * KC;           // 2048
    const int xblocks = (M / 128) * KC;           // 4096
    prepass_kernel<<<wblocks + xblocks, 256>>>(x, wq, scale, K, KC, wblocks);

    int nsm = 148;
    cudaDeviceGetAttribute(&nsm, cudaDevAttrMultiProcessorCount, 0);

    cudaFuncSetAttribute(gemm_kernel,
                         cudaFuncAttributeMaxDynamicSharedMemorySize,
                         SMEM_TOTAL_GEMM);
    gemm_kernel<<<nsm, THREADS, SMEM_TOTAL_GEMM>>>(bias, out, M, N, K, ntiles);
}

// round 15
// speedup vs baseline: 1.0937x; 1.0937x over previous
#include <cuda_runtime.h>
#include <cuda_fp16.h>
#include <cstdint>

// ============================================================================
// INT4Linear on GB300 — R13 champion + L2-protection cache hints.
//   out[M,N] = x[M,K] @ W[N,K]^T + bias     M=8192 N=4096 K=4096
// R14 post-mortem: cg1 bigger tiles re-read B (2 MMAs/k-step) -> 128x256
// double-buffered is traffic-optimal; R13 runs at the port-model limit.
// This round: evict-first streaming for the 128MB output (__stcs) and the
// 192MB once-read prepass inputs (__ldcs) so operands stay L2-resident
// (R13 showed ~120MB operand refetch from output-induced eviction).
// Everything else byte-identical to R13 (225.2us best).
// ============================================================================

#if defined(__CUDA_ARCH_FEAT_SM103_ALL) || defined(__CUDA_ARCH_FEAT_SM100_ALL)
#define TC_PATH 1
#else
#define TC_PATH 0
#endif

#define KC_ELEMS 64
#define BLK_BYTES 16384
#define STAGES 4
#define STAGE_BYTES (3 * BLK_BYTES)   // A 16KB + B 32KB
#define SMEM_STAGE0 1024
#define SMEM_TOTAL_GEMM (SMEM_STAGE0 + STAGES * STAGE_BYTES)   // 197632
#define THREADS 320
#define NB_GROUP 4                    // supertile width in nb

__device__ __half g_W[4096u * 4096u];   // 32 MB, [N/256][K/64][2][128x64] SW128
__device__ __half g_X[8192u * 4096u];   // 64 MB, [M/128][K/64][128x64] SW128

__host__ __device__ __forceinline__ uint32_t swz128(uint32_t o) {
    return o ^ ((o >> 3) & 0x70);
}
__device__ __forceinline__ uint32_t smem_u32(const void* p) {
    return (uint32_t)__cvta_generic_to_shared(p);
}
// L2-aware tile order: groups of NB_GROUP nb-columns, mb-major inside a group.
__device__ __forceinline__ void tile_coords(int t, int TILES_M, int& mb, int& nb) {
    const int per_group = TILES_M * NB_GROUP;       // 256
    const int g = t / per_group;
    const int r = t - g * per_group;
    mb = r >> 2;                                     // r / NB_GROUP
    nb = g * NB_GROUP + (r & (NB_GROUP - 1));
}

// ---------------------------------------------------------------------------
#if TC_PATH
__device__ __forceinline__ void mbar_init(uint32_t a, uint32_t cnt) {
    asm volatile("mbarrier.init.shared.b64 [%0], %1;" :: "r"(a), "r"(cnt) : "memory");
}
__device__ __forceinline__ void mbar_arrive(uint32_t a) {
    asm volatile("mbarrier.arrive.shared.b64 _, [%0];" :: "r"(a) : "memory");
}
__device__ __forceinline__ void mbar_expect_tx(uint32_t a, uint32_t bytes) {
    asm volatile("mbarrier.arrive.expect_tx.shared.b64 _, [%0], %1;"
                 :: "r"(a), "r"(bytes) : "memory");
}
__device__ __forceinline__ void mbar_wait(uint32_t a, uint32_t parity) {
    uint32_t done;
    asm volatile(
        "{\n\t.reg .pred p;\n\t"
        "mbarrier.try_wait.parity.acquire.cta.shared::cta.b64 p, [%1], %2;\n\t"
        "selp.b32 %0, 1, 0, p;\n\t}"
        : "=r"(done) : "r"(a), "r"(parity) : "memory");
    if (!done) {
        asm volatile(
            "{\n\t.reg .pred P1;\n\t"
            "W0_%=:\n\t"
            "mbarrier.try_wait.parity.acquire.cta.shared::cta.b64 P1, [%0], %1, 0x989680;\n\t"
            "@P1 bra.uni W1_%=;\n\t"
            "bra.uni W0_%=;\n\t"
            "W1_%=:\n\t}"
            :: "r"(a), "r"(parity) : "memory");
    }
}
__device__ __forceinline__ void bulk_g2s(uint32_t dst, const void* src,
                                         uint32_t bytes, uint32_t mbar) {
    asm volatile(
        "cp.async.bulk.shared::cluster.global.mbarrier::complete_tx::bytes "
        "[%0], [%1], %2, [%3];"
        :: "r"(dst), "l"(src), "r"(bytes), "r"(mbar) : "memory");
}
__device__ __forceinline__ void tmem_alloc(uint32_t smem_slot, uint32_t ncols) {
    asm volatile("tcgen05.alloc.cta_group::1.sync.aligned.shared::cta.b32 [%0], %1;"
                 :: "r"(smem_slot), "r"(ncols) : "memory");
}
__device__ __forceinline__ void tmem_relinquish() {
    asm volatile("tcgen05.relinquish_alloc_permit.cta_group::1.sync.aligned;");
}
__device__ __forceinline__ void tmem_dealloc(uint32_t base, uint32_t ncols) {
    asm volatile("tcgen05.dealloc.cta_group::1.sync.aligned.b32 %0, %1;"
                 :: "r"(base), "r"(ncols));
}
__device__ __forceinline__ void mma_f16_ss(uint32_t d_tmem, uint64_t a_desc,
                                           uint64_t b_desc, uint32_t idesc,
                                           uint32_t enable) {
    asm volatile(
        "{\n\t.reg .pred p;\n\t"
        "setp.ne.u32 p, %5, 0;\n\t"
        "tcgen05.mma.cta_group::1.kind::f16 [%0], %1, %2, %3, {%4, %4, %4, %4}, p;\n\t}"
        :: "r"(d_tmem), "l"(a_desc), "l"(b_desc), "r"(idesc), "r"(0u), "r"(enable)
        : "memory");
}
__device__ __forceinline__ void tc_commit(uint32_t mbar) {
    asm volatile(
        "tcgen05.commit.cta_group::1.mbarrier::arrive::one.shared::cluster.b64 [%0];"
        :: "r"(mbar) : "memory");
}
__device__ __forceinline__ void tc_fence_after() {
    asm volatile("tcgen05.fence::after_thread_sync;" ::: "memory");
}
__device__ __forceinline__ void tc_fence_before() {
    asm volatile("tcgen05.fence::before_thread_sync;" ::: "memory");
}
__device__ __forceinline__ void ldtm_x32(uint32_t* r, uint32_t addr) {
    asm volatile(
        "tcgen05.ld.sync.aligned.32x32b.x32.b32 "
        "{%0,%1,%2,%3,%4,%5,%6,%7,%8,%9,%10,%11,%12,%13,%14,%15,"
        "%16,%17,%18,%19,%20,%21,%22,%23,%24,%25,%26,%27,%28,%29,%30,%31}, [%32];"
        : "=r"(r[0]), "=r"(r[1]), "=r"(r[2]), "=r"(r[3]),
          "=r"(r[4]), "=r"(r[5]), "=r"(r[6]), "=r"(r[7]),
          "=r"(r[8]), "=r"(r[9]), "=r"(r[10]), "=r"(r[11]),
          "=r"(r[12]), "=r"(r[13]), "=r"(r[14]), "=r"(r[15]),
          "=r"(r[16]), "=r"(r[17]), "=r"(r[18]), "=r"(r[19]),
          "=r"(r[20]), "=r"(r[21]), "=r"(r[22]), "=r"(r[23]),
          "=r"(r[24]), "=r"(r[25]), "=r"(r[26]), "=r"(r[27]),
          "=r"(r[28]), "=r"(r[29]), "=r"(r[30]), "=r"(r[31])
        : "r"(addr));
}
__device__ __forceinline__ void tc_wait_ld() {
    asm volatile("tcgen05.wait::ld.sync.aligned;" ::: "memory");
}
// SW128 K-major SMEM descriptor (version=1, LBO=1, SBO=64)
__device__ __forceinline__ uint64_t make_desc(uint32_t smem_addr) {
    const uint64_t base =
        (uint64_t(2) << 61) | (uint64_t(1) << 46) | (uint64_t(64) << 32) | (uint64_t(1) << 16);
    return base | ((uint64_t)(smem_addr >> 4) & 0x3FFF);
}
// idesc cg1: dtype F32 (1<<4), fp16 a/b, N=256 (32<<17), M=128 (8<<24)
#define IDESC 0x8400010u
#endif  // TC_PATH

// ---------------------------------------------------------------------------
// k1: fused prepass (R10-proven) with streaming (__ldcs) input reads.
// ---------------------------------------------------------------------------
__global__ __launch_bounds__(256)
void prepass_kernel(const float* __restrict__ x,
                    const int* __restrict__ packed,
                    const float* __restrict__ scale_p,
                    int K, int KC, int wblocks) {
    const int bid = blockIdx.x;
    const int tid = threadIdx.x;

    if (bid < wblocks) {
        const float s = __ldg(scale_p);
        const int K2 = K >> 1;
        const int nkc  = bid >> 1;
        const int half = bid & 1;
        const int n2 = nkc / KC;
        const int kc = nkc - n2 * KC;
        const int nbase = n2 * 256 + half * 128;
        char* outb = reinterpret_cast<char*>(g_W) + (size_t)bid * BLK_BYTES;

#pragma unroll
        for (int it = 0; it < 4; ++it) {
            const int u   = tid + it * 256;
            const int row = u >> 3;
            const int cg  = u & 7;
            const int4 v = __ldcs(reinterpret_cast<const int4*>(
                packed + (size_t)(nbase + row) * K2 + kc * 32 + cg * 4));
            __half o[8];
            const int b4[4] = {v.x, v.y, v.z, v.w};
#pragma unroll
            for (int j = 0; j < 4; ++j) {
                int hi = b4[j] >> 4;
                int lo = ((b4[j] & 15) ^ 8) - 8;
                o[2 * j]     = __float2half_rn((float)hi * s);
                o[2 * j + 1] = __float2half_rn((float)lo * s);
            }
            *reinterpret_cast<uint4*>(outb + swz128((uint32_t)(row * 128 + cg * 16))) =
                *reinterpret_cast<const uint4*>(o);
        }
    } else {
        const int xb = bid - wblocks;
        const int mb = xb / KC;
        const int kc = xb - mb * KC;
        const float* xin = x + (size_t)(mb * 128) * K + kc * 64;
        char* outb = reinterpret_cast<char*>(g_X) + (size_t)xb * BLK_BYTES;

#pragma unroll
        for (int it = 0; it < 4; ++it) {
            const int u   = tid + it * 256;
            const int row = u >> 3;
            const int cg  = u & 7;
            const float4* src = reinterpret_cast<const float4*>(
                xin + (size_t)row * K + cg * 8);
            const float4 a = __ldcs(src);
            const float4 c = __ldcs(src + 1);
            __half o[8];
            o[0] = __float2half_rn(a.x); o[1] = __float2half_rn(a.y);
            o[2] = __float2half_rn(a.z); o[3] = __float2half_rn(a.w);
            o[4] = __float2half_rn(c.x); o[5] = __float2half_rn(c.y);
            o[6] = __float2half_rn(c.z); o[7] = __float2half_rn(c.w);
            *reinterpret_cast<uint4*>(outb + swz128((uint32_t)(row * 128 + cg * 16))) =
                *reinterpret_cast<const uint4*>(o);
        }
    }
}

// ---------------------------------------------------------------------------
// k2: persistent GEMM (R13 structure), supertile order, streaming stores.
// smem: full[4]@0, empty[4]@32, done[2]@64, efree[2]@80, tslot@96, stages@1024.
// ---------------------------------------------------------------------------
__global__ __launch_bounds__(THREADS, 1)
void gemm_kernel(const float* __restrict__ bias,
                 float* __restrict__ Out,
                 int M, int N, int K, int ntiles) {
    extern __shared__ char smem[];
    const uint32_t sbase = smem_u32(smem);
    const int tid  = threadIdx.x;
    const int wid  = tid >> 5;
    const int lane = tid & 31;

    const int KC      = K / KC_ELEMS;            // 64
    const int TILES_M = M / 128;                 // 64

#if TC_PATH
    const uint32_t full0  = sbase;
    const uint32_t empty0 = sbase + 32;
    const uint32_t done0  = sbase + 64;
    const uint32_t efree0 = sbase + 80;
    const uint32_t tslot  = sbase + 96;

    if (tid == 0) {
#pragma unroll
        for (int s = 0; s < STAGES; ++s) {
            mbar_init(full0 + s * 8, 1);
            mbar_init(empty0 + s * 8, 1);
        }
        mbar_init(done0, 1);     mbar_init(done0 + 8, 1);
        mbar_init(efree0, 8);    mbar_init(efree0 + 8, 8);
    }
    __syncthreads();

    if (wid == 8) {
        tmem_alloc(tslot, 512);
        tmem_relinquish();
    }
    __syncthreads();
    uint32_t tmem_base;
    asm volatile("ld.shared.b32 %0, [%1];" : "=r"(tmem_base) : "r"(tslot));

    // ==================== producer: warp 8, lane 0 ====================
    if (tid == 256) {
        int s = 0, ph = 1;
        for (int t = blockIdx.x; t < ntiles; t += gridDim.x) {
            int mb, nb;
            tile_coords(t, TILES_M, mb, nb);
            const char* Asrc = reinterpret_cast<const char*>(g_X) +
                               (size_t)mb * KC * BLK_BYTES;
            const char* Bsrc = reinterpret_cast<const char*>(g_W) +
                               (size_t)nb * KC * 2 * BLK_BYTES;
            for (int i = 0; i < KC; ++i) {
                mbar_wait(empty0 + s * 8, ph);
                const uint32_t fb = full0 + s * 8;
                mbar_expect_tx(fb, STAGE_BYTES);
                const uint32_t stg = sbase + SMEM_STAGE0 + s * STAGE_BYTES;
                bulk_g2s(stg,             Asrc + (size_t)i * BLK_BYTES,     BLK_BYTES,     fb);
                bulk_g2s(stg + BLK_BYTES, Bsrc + (size_t)i * 2 * BLK_BYTES, 2 * BLK_BYTES, fb);
                if (++s == STAGES) { s = 0; ph ^= 1; }
            }
        }
    }

    // ==================== MMA issuer: warp 9, lane 0 ====================
    if (tid == 288) {
        int s = 0, ph = 0;
        int j = 0;
        for (int t = blockIdx.x; t < ntiles; t += gridDim.x, ++j) {
            const int buf = j & 1;
            const int u   = j >> 1;
            if (u > 0) mbar_wait(efree0 + buf * 8, (u - 1) & 1);
            tc_fence_after();
            const uint32_t dacc = tmem_base + buf * 256;
            for (int i = 0; i < KC; ++i) {
                mbar_wait(full0 + s * 8, ph);
                const uint32_t stg = sbase + SMEM_STAGE0 + s * STAGE_BYTES;
                uint64_t ad = make_desc(stg);
                uint64_t bd = make_desc(stg + BLK_BYTES);
#pragma unroll
                for (int ks = 0; ks < 4; ++ks) {
                    mma_f16_ss(dacc, ad + ks * 2, bd + ks * 2, IDESC,
                               (i > 0 || ks > 0) ? 1u : 0u);
                }
                tc_commit(empty0 + s * 8);
                if (++s == STAGES) { s = 0; ph ^= 1; }
            }
            tc_commit(done0 + buf * 8);
        }
    }

    // ==================== epilogue: warps 0-7 ====================
    if (wid < 8) {
        const int subp    = wid & 3;
        const int colhalf = wid >> 2;
        int j = 0;
        for (int t = blockIdx.x; t < ntiles; t += gridDim.x, ++j) {
            const int buf = j & 1;
            const int u   = j >> 1;
            mbar_wait(done0 + buf * 8, u & 1);
            tc_fence_after();

            int mb, nb;
            tile_coords(t, TILES_M, mb, nb);
            const int row = mb * 128 + subp * 32 + lane;
            float* orow = Out + (size_t)row * N + nb * 256 + colhalf * 128;
            const float* brow = bias + nb * 256 + colhalf * 128;
            const uint32_t tacc = tmem_base + buf * 256 + colhalf * 128;

#pragma unroll
            for (int cb = 0; cb < 4; ++cb) {
                uint32_t r32[32];
                ldtm_x32(r32, tacc + cb * 32);
                tc_wait_ld();
                float o[32];
#pragma unroll
                for (int q = 0; q < 8; ++q) {
                    const float4 bf = *reinterpret_cast<const float4*>(brow + cb * 32 + q * 4);
                    const float bfv[4] = {bf.x, bf.y, bf.z, bf.w};
#pragma unroll
                    for (int e = 0; e < 4; ++e) {
                        const int c = q * 4 + e;
                        __half h  = __float2half_rn(__uint_as_float(r32[c]));
                        __half hb = __float2half_rn(bfv[e]);
                        o[c] = __half2float(__hadd(h, hb));
                    }
                }
#pragma unroll
                for (int q = 0; q < 8; ++q) {
                    __stcs(reinterpret_cast<float4*>(orow + cb * 32) + q,
                           make_float4(o[4 * q], o[4 * q + 1], o[4 * q + 2], o[4 * q + 3]));
                }
            }
            tc_fence_before();
            if (lane == 0) mbar_arrive(efree0 + buf * 8);
        }
    }

    __syncthreads();
    if (wid == 8) tmem_dealloc(tmem_base, 512);

#else
    // =============== compile-only fallback (never selected on GB300) =======
    for (int t = blockIdx.x; t < ntiles; t += gridDim.x) {
        int mb, nb;
        tile_coords(t, TILES_M, mb, nb);
        for (int rr = tid; rr < 128; rr += THREADS) {
            const int m = mb * 128 + rr;
            for (int c = 0; c < 256; ++c) {
                const int n = nb * 256 + c;
                float acc = 0.0f;
                for (int k = 0; k < K; ++k) {
                    size_t ablk = (size_t)(m >> 7) * KC + (k >> 6);
                    const __half* ae = reinterpret_cast<const __half*>(
                        reinterpret_cast<const char*>(g_X) + ablk * BLK_BYTES +
                        swz128((uint32_t)((m & 127) * 128 + (k & 63) * 2)));
                    size_t bblk = ((size_t)(n >> 8) * KC + (k >> 6)) * 2 + ((n >> 7) & 1);
                    const __half* be = reinterpret_cast<const __half*>(
                        reinterpret_cast<const char*>(g_W) + bblk * BLK_BYTES +
                        swz128((uint32_t)((n & 127) * 128 + (k & 63) * 2)));
                    acc += __half2float(*ae) * __half2float(*be);
                }
                __half h = __hadd(__float2half_rn(acc), __float2half_rn(bias[n]));
                Out[(size_t)m * N + n] = __half2float(h);
            }
        }
    }
#endif
}

// ---------------------------------------------------------------------------
extern "C" void kernel_launch(void* const* d_in, const int* in_sizes, int n_in,
                              void* d_out, int out_size) {
    const float* x     = (const float*)d_in[0];
    const int*   wq    = (const int*)d_in[1];
    const float* scale = (const float*)d_in[2];
    const float* bias  = (const float*)d_in[3];
    float*       out   = (float*)d_out;

    const int O = in_sizes[3];                    // 4096
    const int K = (in_sizes[1] / O) * 2;          // 4096
    const int M = in_sizes[0] / K;                // 8192
    const int N = O;
    const int KC = K / KC_ELEMS;                  // 64
    const int ntiles = (M / 128) * (N / 256);     // 1024

    const int wblocks = (N / 128) * KC;           // 2048
    const int xblocks = (M / 128) * KC;           // 4096
    prepass_kernel<<<wblocks + xblocks, 256>>>(x, wq, scale, K, KC, wblocks);

    int nsm = 148;
    cudaDeviceGetAttribute(&nsm, cudaDevAttrMultiProcessorCount, 0);

    cudaFuncSetAttribute(gemm_kernel,
                         cudaFuncAttributeMaxDynamicSharedMemorySize,
                         SMEM_TOTAL_GEMM);
    gemm_kernel<<<nsm, THREADS, SMEM_TOTAL_GEMM>>>(bias, out, M, N, K, ntiles);
}

// round 16
// speedup vs baseline: 1.1214x; 1.0254x over previous
#include <cuda_runtime.h>
#include <cuda_fp16.h>
#include <cstdint>

// ============================================================================
// INT4Linear on GB300 — R13 champion, NB_GROUP=8 supertiles.
//   out[M,N] = x[M,K] @ W[N,K]^T + bias     M=8192 N=4096 K=4096
// R15: cache hints neutral (GEMM) / slightly negative (prepass) -> reverted.
// R13 DRAM accounting: 347MB = A 64MB x (16 nb / NB_GROUP 4) + B + first
// touch. NB_GROUP=8 halves A refetch (256->128MB); working set 35MB << L2.
// k1: fused prepass (R10-proven). k2: persistent tcgen05 cg1 128x256,
// 4-stage pipeline, double-buffered TMEM, supertile tile order.
// ============================================================================

#if defined(__CUDA_ARCH_FEAT_SM103_ALL) || defined(__CUDA_ARCH_FEAT_SM100_ALL)
#define TC_PATH 1
#else
#define TC_PATH 0
#endif

#define KC_ELEMS 64
#define BLK_BYTES 16384
#define STAGES 4
#define STAGE_BYTES (3 * BLK_BYTES)   // A 16KB + B 32KB
#define SMEM_STAGE0 1024
#define SMEM_TOTAL_GEMM (SMEM_STAGE0 + STAGES * STAGE_BYTES)   // 197632
#define THREADS 320
#define NB_GROUP 8                    // supertile width in nb

__device__ __half g_W[4096u * 4096u];   // 32 MB, [N/256][K/64][2][128x64] SW128
__device__ __half g_X[8192u * 4096u];   // 64 MB, [M/128][K/64][128x64] SW128

__host__ __device__ __forceinline__ uint32_t swz128(uint32_t o) {
    return o ^ ((o >> 3) & 0x70);
}
__device__ __forceinline__ uint32_t smem_u32(const void* p) {
    return (uint32_t)__cvta_generic_to_shared(p);
}
// L2-aware tile order: groups of NB_GROUP nb-columns, mb-major inside a group.
__device__ __forceinline__ void tile_coords(int t, int TILES_M, int& mb, int& nb) {
    const int per_group = TILES_M * NB_GROUP;       // 512
    const int g = t / per_group;
    const int r = t - g * per_group;
    mb = r >> 3;                                     // r / NB_GROUP
    nb = g * NB_GROUP + (r & (NB_GROUP - 1));
}

// ---------------------------------------------------------------------------
#if TC_PATH
__device__ __forceinline__ void mbar_init(uint32_t a, uint32_t cnt) {
    asm volatile("mbarrier.init.shared.b64 [%0], %1;" :: "r"(a), "r"(cnt) : "memory");
}
__device__ __forceinline__ void mbar_arrive(uint32_t a) {
    asm volatile("mbarrier.arrive.shared.b64 _, [%0];" :: "r"(a) : "memory");
}
__device__ __forceinline__ void mbar_expect_tx(uint32_t a, uint32_t bytes) {
    asm volatile("mbarrier.arrive.expect_tx.shared.b64 _, [%0], %1;"
                 :: "r"(a), "r"(bytes) : "memory");
}
__device__ __forceinline__ void mbar_wait(uint32_t a, uint32_t parity) {
    uint32_t done;
    asm volatile(
        "{\n\t.reg .pred p;\n\t"
        "mbarrier.try_wait.parity.acquire.cta.shared::cta.b64 p, [%1], %2;\n\t"
        "selp.b32 %0, 1, 0, p;\n\t}"
        : "=r"(done) : "r"(a), "r"(parity) : "memory");
    if (!done) {
        asm volatile(
            "{\n\t.reg .pred P1;\n\t"
            "W0_%=:\n\t"
            "mbarrier.try_wait.parity.acquire.cta.shared::cta.b64 P1, [%0], %1, 0x989680;\n\t"
            "@P1 bra.uni W1_%=;\n\t"
            "bra.uni W0_%=;\n\t"
            "W1_%=:\n\t}"
            :: "r"(a), "r"(parity) : "memory");
    }
}
__device__ __forceinline__ void bulk_g2s(uint32_t dst, const void* src,
                                         uint32_t bytes, uint32_t mbar) {
    asm volatile(
        "cp.async.bulk.shared::cluster.global.mbarrier::complete_tx::bytes "
        "[%0], [%1], %2, [%3];"
        :: "r"(dst), "l"(src), "r"(bytes), "r"(mbar) : "memory");
}
__device__ __forceinline__ void tmem_alloc(uint32_t smem_slot, uint32_t ncols) {
    asm volatile("tcgen05.alloc.cta_group::1.sync.aligned.shared::cta.b32 [%0], %1;"
                 :: "r"(smem_slot), "r"(ncols) : "memory");
}
__device__ __forceinline__ void tmem_relinquish() {
    asm volatile("tcgen05.relinquish_alloc_permit.cta_group::1.sync.aligned;");
}
__device__ __forceinline__ void tmem_dealloc(uint32_t base, uint32_t ncols) {
    asm volatile("tcgen05.dealloc.cta_group::1.sync.aligned.b32 %0, %1;"
                 :: "r"(base), "r"(ncols));
}
__device__ __forceinline__ void mma_f16_ss(uint32_t d_tmem, uint64_t a_desc,
                                           uint64_t b_desc, uint32_t idesc,
                                           uint32_t enable) {
    asm volatile(
        "{\n\t.reg .pred p;\n\t"
        "setp.ne.u32 p, %5, 0;\n\t"
        "tcgen05.mma.cta_group::1.kind::f16 [%0], %1, %2, %3, {%4, %4, %4, %4}, p;\n\t}"
        :: "r"(d_tmem), "l"(a_desc), "l"(b_desc), "r"(idesc), "r"(0u), "r"(enable)
        : "memory");
}
__device__ __forceinline__ void tc_commit(uint32_t mbar) {
    asm volatile(
        "tcgen05.commit.cta_group::1.mbarrier::arrive::one.shared::cluster.b64 [%0];"
        :: "r"(mbar) : "memory");
}
__device__ __forceinline__ void tc_fence_after() {
    asm volatile("tcgen05.fence::after_thread_sync;" ::: "memory");
}
__device__ __forceinline__ void tc_fence_before() {
    asm volatile("tcgen05.fence::before_thread_sync;" ::: "memory");
}
__device__ __forceinline__ void ldtm_x32(uint32_t* r, uint32_t addr) {
    asm volatile(
        "tcgen05.ld.sync.aligned.32x32b.x32.b32 "
        "{%0,%1,%2,%3,%4,%5,%6,%7,%8,%9,%10,%11,%12,%13,%14,%15,"
        "%16,%17,%18,%19,%20,%21,%22,%23,%24,%25,%26,%27,%28,%29,%30,%31}, [%32];"
        : "=r"(r[0]), "=r"(r[1]), "=r"(r[2]), "=r"(r[3]),
          "=r"(r[4]), "=r"(r[5]), "=r"(r[6]), "=r"(r[7]),
          "=r"(r[8]), "=r"(r[9]), "=r"(r[10]), "=r"(r[11]),
          "=r"(r[12]), "=r"(r[13]), "=r"(r[14]), "=r"(r[15]),
          "=r"(r[16]), "=r"(r[17]), "=r"(r[18]), "=r"(r[19]),
          "=r"(r[20]), "=r"(r[21]), "=r"(r[22]), "=r"(r[23]),
          "=r"(r[24]), "=r"(r[25]), "=r"(r[26]), "=r"(r[27]),
          "=r"(r[28]), "=r"(r[29]), "=r"(r[30]), "=r"(r[31])
        : "r"(addr));
}
__device__ __forceinline__ void tc_wait_ld() {
    asm volatile("tcgen05.wait::ld.sync.aligned;" ::: "memory");
}
// SW128 K-major SMEM descriptor (version=1, LBO=1, SBO=64)
__device__ __forceinline__ uint64_t make_desc(uint32_t smem_addr) {
    const uint64_t base =
        (uint64_t(2) << 61) | (uint64_t(1) << 46) | (uint64_t(64) << 32) | (uint64_t(1) << 16);
    return base | ((uint64_t)(smem_addr >> 4) & 0x3FFF);
}
// idesc cg1: dtype F32 (1<<4), fp16 a/b, N=256 (32<<17), M=128 (8<<24)
#define IDESC 0x8400010u
#endif  // TC_PATH

// ---------------------------------------------------------------------------
// k1: fused prepass (R10-proven). Block bid < wblocks: W block; else X block.
// ---------------------------------------------------------------------------
__global__ __launch_bounds__(256)
void prepass_kernel(const float* __restrict__ x,
                    const int* __restrict__ packed,
                    const float* __restrict__ scale_p,
                    int K, int KC, int wblocks) {
    const int bid = blockIdx.x;
    const int tid = threadIdx.x;

    if (bid < wblocks) {
        const float s = __ldg(scale_p);
        const int K2 = K >> 1;
        const int nkc  = bid >> 1;
        const int half = bid & 1;
        const int n2 = nkc / KC;
        const int kc = nkc - n2 * KC;
        const int nbase = n2 * 256 + half * 128;
        char* outb = reinterpret_cast<char*>(g_W) + (size_t)bid * BLK_BYTES;

#pragma unroll
        for (int it = 0; it < 4; ++it) {
            const int u   = tid + it * 256;
            const int row = u >> 3;
            const int cg  = u & 7;
            const int4 v = *reinterpret_cast<const int4*>(
                packed + (size_t)(nbase + row) * K2 + kc * 32 + cg * 4);
            __half o[8];
            const int b4[4] = {v.x, v.y, v.z, v.w};
#pragma unroll
            for (int j = 0; j < 4; ++j) {
                int hi = b4[j] >> 4;
                int lo = ((b4[j] & 15) ^ 8) - 8;
                o[2 * j]     = __float2half_rn((float)hi * s);
                o[2 * j + 1] = __float2half_rn((float)lo * s);
            }
            *reinterpret_cast<uint4*>(outb + swz128((uint32_t)(row * 128 + cg * 16))) =
                *reinterpret_cast<const uint4*>(o);
        }
    } else {
        const int xb = bid - wblocks;
        const int mb = xb / KC;
        const int kc = xb - mb * KC;
        const float* xin = x + (size_t)(mb * 128) * K + kc * 64;
        char* outb = reinterpret_cast<char*>(g_X) + (size_t)xb * BLK_BYTES;

#pragma unroll
        for (int it = 0; it < 4; ++it) {
            const int u   = tid + it * 256;
            const int row = u >> 3;
            const int cg  = u & 7;
            const float4* src = reinterpret_cast<const float4*>(
                xin + (size_t)row * K + cg * 8);
            const float4 a = src[0];
            const float4 c = src[1];
            __half o[8];
            o[0] = __float2half_rn(a.x); o[1] = __float2half_rn(a.y);
            o[2] = __float2half_rn(a.z); o[3] = __float2half_rn(a.w);
            o[4] = __float2half_rn(c.x); o[5] = __float2half_rn(c.y);
            o[6] = __float2half_rn(c.z); o[7] = __float2half_rn(c.w);
            *reinterpret_cast<uint4*>(outb + swz128((uint32_t)(row * 128 + cg * 16))) =
                *reinterpret_cast<const uint4*>(o);
        }
    }
}

// ---------------------------------------------------------------------------
// k2: persistent GEMM (R13 structure), NB_GROUP=8 supertile order.
// smem: full[4]@0, empty[4]@32, done[2]@64, efree[2]@80, tslot@96, stages@1024.
// ---------------------------------------------------------------------------
__global__ __launch_bounds__(THREADS, 1)
void gemm_kernel(const float* __restrict__ bias,
                 float* __restrict__ Out,
                 int M, int N, int K, int ntiles) {
    extern __shared__ char smem[];
    const uint32_t sbase = smem_u32(smem);
    const int tid  = threadIdx.x;
    const int wid  = tid >> 5;
    const int lane = tid & 31;

    const int KC      = K / KC_ELEMS;            // 64
    const int TILES_M = M / 128;                 // 64

#if TC_PATH
    const uint32_t full0  = sbase;
    const uint32_t empty0 = sbase + 32;
    const uint32_t done0  = sbase + 64;
    const uint32_t efree0 = sbase + 80;
    const uint32_t tslot  = sbase + 96;

    if (tid == 0) {
#pragma unroll
        for (int s = 0; s < STAGES; ++s) {
            mbar_init(full0 + s * 8, 1);
            mbar_init(empty0 + s * 8, 1);
        }
        mbar_init(done0, 1);     mbar_init(done0 + 8, 1);
        mbar_init(efree0, 8);    mbar_init(efree0 + 8, 8);
    }
    __syncthreads();

    if (wid == 8) {
        tmem_alloc(tslot, 512);
        tmem_relinquish();
    }
    __syncthreads();
    uint32_t tmem_base;
    asm volatile("ld.shared.b32 %0, [%1];" : "=r"(tmem_base) : "r"(tslot));

    // ==================== producer: warp 8, lane 0 ====================
    if (tid == 256) {
        int s = 0, ph = 1;
        for (int t = blockIdx.x; t < ntiles; t += gridDim.x) {
            int mb, nb;
            tile_coords(t, TILES_M, mb, nb);
            const char* Asrc = reinterpret_cast<const char*>(g_X) +
                               (size_t)mb * KC * BLK_BYTES;
            const char* Bsrc = reinterpret_cast<const char*>(g_W) +
                               (size_t)nb * KC * 2 * BLK_BYTES;
            for (int i = 0; i < KC; ++i) {
                mbar_wait(empty0 + s * 8, ph);
                const uint32_t fb = full0 + s * 8;
                mbar_expect_tx(fb, STAGE_BYTES);
                const uint32_t stg = sbase + SMEM_STAGE0 + s * STAGE_BYTES;
                bulk_g2s(stg,             Asrc + (size_t)i * BLK_BYTES,     BLK_BYTES,     fb);
                bulk_g2s(stg + BLK_BYTES, Bsrc + (size_t)i * 2 * BLK_BYTES, 2 * BLK_BYTES, fb);
                if (++s == STAGES) { s = 0; ph ^= 1; }
            }
        }
    }

    // ==================== MMA issuer: warp 9, lane 0 ====================
    if (tid == 288) {
        int s = 0, ph = 0;
        int j = 0;
        for (int t = blockIdx.x; t < ntiles; t += gridDim.x, ++j) {
            const int buf = j & 1;
            const int u   = j >> 1;
            if (u > 0) mbar_wait(efree0 + buf * 8, (u - 1) & 1);
            tc_fence_after();
            const uint32_t dacc = tmem_base + buf * 256;
            for (int i = 0; i < KC; ++i) {
                mbar_wait(full0 + s * 8, ph);
                const uint32_t stg = sbase + SMEM_STAGE0 + s * STAGE_BYTES;
                uint64_t ad = make_desc(stg);
                uint64_t bd = make_desc(stg + BLK_BYTES);
#pragma unroll
                for (int ks = 0; ks < 4; ++ks) {
                    mma_f16_ss(dacc, ad + ks * 2, bd + ks * 2, IDESC,
                               (i > 0 || ks > 0) ? 1u : 0u);
                }
                tc_commit(empty0 + s * 8);
                if (++s == STAGES) { s = 0; ph ^= 1; }
            }
            tc_commit(done0 + buf * 8);
        }
    }

    // ==================== epilogue: warps 0-7 ====================
    if (wid < 8) {
        const int subp    = wid & 3;
        const int colhalf = wid >> 2;
        int j = 0;
        for (int t = blockIdx.x; t < ntiles; t += gridDim.x, ++j) {
            const int buf = j & 1;
            const int u   = j >> 1;
            mbar_wait(done0 + buf * 8, u & 1);
            tc_fence_after();

            int mb, nb;
            tile_coords(t, TILES_M, mb, nb);
            const int row = mb * 128 + subp * 32 + lane;
            float* orow = Out + (size_t)row * N + nb * 256 + colhalf * 128;
            const float* brow = bias + nb * 256 + colhalf * 128;
            const uint32_t tacc = tmem_base + buf * 256 + colhalf * 128;

#pragma unroll
            for (int cb = 0; cb < 4; ++cb) {
                uint32_t r32[32];
                ldtm_x32(r32, tacc + cb * 32);
                tc_wait_ld();
                float o[32];
#pragma unroll
                for (int q = 0; q < 8; ++q) {
                    const float4 bf = *reinterpret_cast<const float4*>(brow + cb * 32 + q * 4);
                    const float bfv[4] = {bf.x, bf.y, bf.z, bf.w};
#pragma unroll
                    for (int e = 0; e < 4; ++e) {
                        const int c = q * 4 + e;
                        __half h  = __float2half_rn(__uint_as_float(r32[c]));
                        __half hb = __float2half_rn(bfv[e]);
                        o[c] = __half2float(__hadd(h, hb));
                    }
                }
#pragma unroll
                for (int q = 0; q < 8; ++q) {
                    reinterpret_cast<float4*>(orow + cb * 32)[q] =
                        make_float4(o[4 * q], o[4 * q + 1], o[4 * q + 2], o[4 * q + 3]);
                }
            }
            tc_fence_before();
            if (lane == 0) mbar_arrive(efree0 + buf * 8);
        }
    }

    __syncthreads();
    if (wid == 8) tmem_dealloc(tmem_base, 512);

#else
    // =============== compile-only fallback (never selected on GB300) =======
    for (int t = blockIdx.x; t < ntiles; t += gridDim.x) {
        int mb, nb;
        tile_coords(t, TILES_M, mb, nb);
        for (int rr = tid; rr < 128; rr += THREADS) {
            const int m = mb * 128 + rr;
            for (int c = 0; c < 256; ++c) {
                const int n = nb * 256 + c;
                float acc = 0.0f;
                for (int k = 0; k < K; ++k) {
                    size_t ablk = (size_t)(m >> 7) * KC + (k >> 6);
                    const __half* ae = reinterpret_cast<const __half*>(
                        reinterpret_cast<const char*>(g_X) + ablk * BLK_BYTES +
                        swz128((uint32_t)((m & 127) * 128 + (k & 63) * 2)));
                    size_t bblk = ((size_t)(n >> 8) * KC + (k >> 6)) * 2 + ((n >> 7) & 1);
                    const __half* be = reinterpret_cast<const __half*>(
                        reinterpret_cast<const char*>(g_W) + bblk * BLK_BYTES +
                        swz128((uint32_t)((n & 127) * 128 + (k & 63) * 2)));
                    acc += __half2float(*ae) * __half2float(*be);
                }
                __half h = __hadd(__float2half_rn(acc), __float2half_rn(bias[n]));
                Out[(size_t)m * N + n] = __half2float(h);
            }
        }
    }
#endif
}

// ---------------------------------------------------------------------------
extern "C" void kernel_launch(void* const* d_in, const int* in_sizes, int n_in,
                              void* d_out, int out_size) {
    const float* x     = (const float*)d_in[0];
    const int*   wq    = (const int*)d_in[1];
    const float* scale = (const float*)d_in[2];
    const float* bias  = (const float*)d_in[3];
    float*       out   = (float*)d_out;

    const int O = in_sizes[3];                    // 4096
    const int K = (in_sizes[1] / O) * 2;          // 4096
    const int M = in_sizes[0] / K;                // 8192
    const int N = O;
    const int KC = K / KC_ELEMS;                  // 64
    const int ntiles = (M / 128) * (N / 256);     // 1024

    const int wblocks = (N / 128) * KC;           // 2048
    const int xblocks = (M / 128) * KC;           // 4096
    prepass_kernel<<<wblocks + xblocks, 256>>>(x, wq, scale, K, KC, wblocks);

    int nsm = 148;
    cudaDeviceGetAttribute(&nsm, cudaDevAttrMultiProcessorCount, 0);

    cudaFuncSetAttribute(gemm_kernel,
                         cudaFuncAttributeMaxDynamicSharedMemorySize,
                         SMEM_TOTAL_GEMM);
    gemm_kernel<<<nsm, THREADS, SMEM_TOTAL_GEMM>>>(bias, out, M, N, K, ntiles);
}

// round 17
// speedup vs baseline: 1.1435x; 1.0197x over previous
#include <cuda_runtime.h>
#include <cuda_fp16.h>
#include <cstdint>

// ============================================================================
// INT4Linear on GB300 — R16 champion, NB_GROUP=16 supertiles.
//   out[M,N] = x[M,K] @ W[N,K]^T + bias     M=8192 N=4096 K=4096
// Verified mechanism (R13: 4-col groups -> -17us; R16: 8 -> -4us): wider
// supertiles cut A-panel DRAM refetch (64MB x 16nb/NB_GROUP). 16 halves it
// again (128->64MB); working set 152 CTAs ~ 9.5mb x 16nb = 42MB << 126MB L2.
// k1: fused prepass (R10-proven, ~DRAM floor). k2: persistent tcgen05 cg1
// 128x256, 4-stage bulk pipeline, double-buffered TMEM, supertile order.
// ============================================================================

#if defined(__CUDA_ARCH_FEAT_SM103_ALL) || defined(__CUDA_ARCH_FEAT_SM100_ALL)
#define TC_PATH 1
#else
#define TC_PATH 0
#endif

#define KC_ELEMS 64
#define BLK_BYTES 16384
#define STAGES 4
#define STAGE_BYTES (3 * BLK_BYTES)   // A 16KB + B 32KB
#define SMEM_STAGE0 1024
#define SMEM_TOTAL_GEMM (SMEM_STAGE0 + STAGES * STAGE_BYTES)   // 197632
#define THREADS 320
#define NB_GROUP 16                   // supertile width in nb

__device__ __half g_W[4096u * 4096u];   // 32 MB, [N/256][K/64][2][128x64] SW128
__device__ __half g_X[8192u * 4096u];   // 64 MB, [M/128][K/64][128x64] SW128

__host__ __device__ __forceinline__ uint32_t swz128(uint32_t o) {
    return o ^ ((o >> 3) & 0x70);
}
__device__ __forceinline__ uint32_t smem_u32(const void* p) {
    return (uint32_t)__cvta_generic_to_shared(p);
}
// L2-aware tile order: groups of NB_GROUP nb-columns, mb-major inside a group.
__device__ __forceinline__ void tile_coords(int t, int TILES_M, int& mb, int& nb) {
    const int per_group = TILES_M * NB_GROUP;       // 1024
    const int g = t / per_group;
    const int r = t - g * per_group;
    mb = r >> 4;                                     // r / NB_GROUP
    nb = g * NB_GROUP + (r & (NB_GROUP - 1));
}

// ---------------------------------------------------------------------------
#if TC_PATH
__device__ __forceinline__ void mbar_init(uint32_t a, uint32_t cnt) {
    asm volatile("mbarrier.init.shared.b64 [%0], %1;" :: "r"(a), "r"(cnt) : "memory");
}
__device__ __forceinline__ void mbar_arrive(uint32_t a) {
    asm volatile("mbarrier.arrive.shared.b64 _, [%0];" :: "r"(a) : "memory");
}
__device__ __forceinline__ void mbar_expect_tx(uint32_t a, uint32_t bytes) {
    asm volatile("mbarrier.arrive.expect_tx.shared.b64 _, [%0], %1;"
                 :: "r"(a), "r"(bytes) : "memory");
}
__device__ __forceinline__ void mbar_wait(uint32_t a, uint32_t parity) {
    uint32_t done;
    asm volatile(
        "{\n\t.reg .pred p;\n\t"
        "mbarrier.try_wait.parity.acquire.cta.shared::cta.b64 p, [%1], %2;\n\t"
        "selp.b32 %0, 1, 0, p;\n\t}"
        : "=r"(done) : "r"(a), "r"(parity) : "memory");
    if (!done) {
        asm volatile(
            "{\n\t.reg .pred P1;\n\t"
            "W0_%=:\n\t"
            "mbarrier.try_wait.parity.acquire.cta.shared::cta.b64 P1, [%0], %1, 0x989680;\n\t"
            "@P1 bra.uni W1_%=;\n\t"
            "bra.uni W0_%=;\n\t"
            "W1_%=:\n\t}"
            :: "r"(a), "r"(parity) : "memory");
    }
}
__device__ __forceinline__ void bulk_g2s(uint32_t dst, const void* src,
                                         uint32_t bytes, uint32_t mbar) {
    asm volatile(
        "cp.async.bulk.shared::cluster.global.mbarrier::complete_tx::bytes "
        "[%0], [%1], %2, [%3];"
        :: "r"(dst), "l"(src), "r"(bytes), "r"(mbar) : "memory");
}
__device__ __forceinline__ void tmem_alloc(uint32_t smem_slot, uint32_t ncols) {
    asm volatile("tcgen05.alloc.cta_group::1.sync.aligned.shared::cta.b32 [%0], %1;"
                 :: "r"(smem_slot), "r"(ncols) : "memory");
}
__device__ __forceinline__ void tmem_relinquish() {
    asm volatile("tcgen05.relinquish_alloc_permit.cta_group::1.sync.aligned;");
}
__device__ __forceinline__ void tmem_dealloc(uint32_t base, uint32_t ncols) {
    asm volatile("tcgen05.dealloc.cta_group::1.sync.aligned.b32 %0, %1;"
                 :: "r"(base), "r"(ncols));
}
__device__ __forceinline__ void mma_f16_ss(uint32_t d_tmem, uint64_t a_desc,
                                           uint64_t b_desc, uint32_t idesc,
                                           uint32_t enable) {
    asm volatile(
        "{\n\t.reg .pred p;\n\t"
        "setp.ne.u32 p, %5, 0;\n\t"
        "tcgen05.mma.cta_group::1.kind::f16 [%0], %1, %2, %3, {%4, %4, %4, %4}, p;\n\t}"
        :: "r"(d_tmem), "l"(a_desc), "l"(b_desc), "r"(idesc), "r"(0u), "r"(enable)
        : "memory");
}
__device__ __forceinline__ void tc_commit(uint32_t mbar) {
    asm volatile(
        "tcgen05.commit.cta_group::1.mbarrier::arrive::one.shared::cluster.b64 [%0];"
        :: "r"(mbar) : "memory");
}
__device__ __forceinline__ void tc_fence_after() {
    asm volatile("tcgen05.fence::after_thread_sync;" ::: "memory");
}
__device__ __forceinline__ void tc_fence_before() {
    asm volatile("tcgen05.fence::before_thread_sync;" ::: "memory");
}
__device__ __forceinline__ void ldtm_x32(uint32_t* r, uint32_t addr) {
    asm volatile(
        "tcgen05.ld.sync.aligned.32x32b.x32.b32 "
        "{%0,%1,%2,%3,%4,%5,%6,%7,%8,%9,%10,%11,%12,%13,%14,%15,"
        "%16,%17,%18,%19,%20,%21,%22,%23,%24,%25,%26,%27,%28,%29,%30,%31}, [%32];"
        : "=r"(r[0]), "=r"(r[1]), "=r"(r[2]), "=r"(r[3]),
          "=r"(r[4]), "=r"(r[5]), "=r"(r[6]), "=r"(r[7]),
          "=r"(r[8]), "=r"(r[9]), "=r"(r[10]), "=r"(r[11]),
          "=r"(r[12]), "=r"(r[13]), "=r"(r[14]), "=r"(r[15]),
          "=r"(r[16]), "=r"(r[17]), "=r"(r[18]), "=r"(r[19]),
          "=r"(r[20]), "=r"(r[21]), "=r"(r[22]), "=r"(r[23]),
          "=r"(r[24]), "=r"(r[25]), "=r"(r[26]), "=r"(r[27]),
          "=r"(r[28]), "=r"(r[29]), "=r"(r[30]), "=r"(r[31])
        : "r"(addr));
}
__device__ __forceinline__ void tc_wait_ld() {
    asm volatile("tcgen05.wait::ld.sync.aligned;" ::: "memory");
}
// SW128 K-major SMEM descriptor (version=1, LBO=1, SBO=64)
__device__ __forceinline__ uint64_t make_desc(uint32_t smem_addr) {
    const uint64_t base =
        (uint64_t(2) << 61) | (uint64_t(1) << 46) | (uint64_t(64) << 32) | (uint64_t(1) << 16);
    return base | ((uint64_t)(smem_addr >> 4) & 0x3FFF);
}
// idesc cg1: dtype F32 (1<<4), fp16 a/b, N=256 (32<<17), M=128 (8<<24)
#define IDESC 0x8400010u
#endif  // TC_PATH

// ---------------------------------------------------------------------------
// k1: fused prepass (R10-proven). Block bid < wblocks: W block; else X block.
// ---------------------------------------------------------------------------
__global__ __launch_bounds__(256)
void prepass_kernel(const float* __restrict__ x,
                    const int* __restrict__ packed,
                    const float* __restrict__ scale_p,
                    int K, int KC, int wblocks) {
    const int bid = blockIdx.x;
    const int tid = threadIdx.x;

    if (bid < wblocks) {
        const float s = __ldg(scale_p);
        const int K2 = K >> 1;
        const int nkc  = bid >> 1;
        const int half = bid & 1;
        const int n2 = nkc / KC;
        const int kc = nkc - n2 * KC;
        const int nbase = n2 * 256 + half * 128;
        char* outb = reinterpret_cast<char*>(g_W) + (size_t)bid * BLK_BYTES;

#pragma unroll
        for (int it = 0; it < 4; ++it) {
            const int u   = tid + it * 256;
            const int row = u >> 3;
            const int cg  = u & 7;
            const int4 v = *reinterpret_cast<const int4*>(
                packed + (size_t)(nbase + row) * K2 + kc * 32 + cg * 4);
            __half o[8];
            const int b4[4] = {v.x, v.y, v.z, v.w};
#pragma unroll
            for (int j = 0; j < 4; ++j) {
                int hi = b4[j] >> 4;
                int lo = ((b4[j] & 15) ^ 8) - 8;
                o[2 * j]     = __float2half_rn((float)hi * s);
                o[2 * j + 1] = __float2half_rn((float)lo * s);
            }
            *reinterpret_cast<uint4*>(outb + swz128((uint32_t)(row * 128 + cg * 16))) =
                *reinterpret_cast<const uint4*>(o);
        }
    } else {
        const int xb = bid - wblocks;
        const int mb = xb / KC;
        const int kc = xb - mb * KC;
        const float* xin = x + (size_t)(mb * 128) * K + kc * 64;
        char* outb = reinterpret_cast<char*>(g_X) + (size_t)xb * BLK_BYTES;

#pragma unroll
        for (int it = 0; it < 4; ++it) {
            const int u   = tid + it * 256;
            const int row = u >> 3;
            const int cg  = u & 7;
            const float4* src = reinterpret_cast<const float4*>(
                xin + (size_t)row * K + cg * 8);
            const float4 a = src[0];
            const float4 c = src[1];
            __half o[8];
            o[0] = __float2half_rn(a.x); o[1] = __float2half_rn(a.y);
            o[2] = __float2half_rn(a.z); o[3] = __float2half_rn(a.w);
            o[4] = __float2half_rn(c.x); o[5] = __float2half_rn(c.y);
            o[6] = __float2half_rn(c.z); o[7] = __float2half_rn(c.w);
            *reinterpret_cast<uint4*>(outb + swz128((uint32_t)(row * 128 + cg * 16))) =
                *reinterpret_cast<const uint4*>(o);
        }
    }
}

// ---------------------------------------------------------------------------
// k2: persistent GEMM (R13/R16 structure), NB_GROUP=16 supertile order.
// smem: full[4]@0, empty[4]@32, done[2]@64, efree[2]@80, tslot@96, stages@1024.
// ---------------------------------------------------------------------------
__global__ __launch_bounds__(THREADS, 1)
void gemm_kernel(const float* __restrict__ bias,
                 float* __restrict__ Out,
                 int M, int N, int K, int ntiles) {
    extern __shared__ char smem[];
    const uint32_t sbase = smem_u32(smem);
    const int tid  = threadIdx.x;
    const int wid  = tid >> 5;
    const int lane = tid & 31;

    const int KC      = K / KC_ELEMS;            // 64
    const int TILES_M = M / 128;                 // 64

#if TC_PATH
    const uint32_t full0  = sbase;
    const uint32_t empty0 = sbase + 32;
    const uint32_t done0  = sbase + 64;
    const uint32_t efree0 = sbase + 80;
    const uint32_t tslot  = sbase + 96;

    if (tid == 0) {
#pragma unroll
        for (int s = 0; s < STAGES; ++s) {
            mbar_init(full0 + s * 8, 1);
            mbar_init(empty0 + s * 8, 1);
        }
        mbar_init(done0, 1);     mbar_init(done0 + 8, 1);
        mbar_init(efree0, 8);    mbar_init(efree0 + 8, 8);
    }
    __syncthreads();

    if (wid == 8) {
        tmem_alloc(tslot, 512);
        tmem_relinquish();
    }
    __syncthreads();
    uint32_t tmem_base;
    asm volatile("ld.shared.b32 %0, [%1];" : "=r"(tmem_base) : "r"(tslot));

    // ==================== producer: warp 8, lane 0 ====================
    if (tid == 256) {
        int s = 0, ph = 1;
        for (int t = blockIdx.x; t < ntiles; t += gridDim.x) {
            int mb, nb;
            tile_coords(t, TILES_M, mb, nb);
            const char* Asrc = reinterpret_cast<const char*>(g_X) +
                               (size_t)mb * KC * BLK_BYTES;
            const char* Bsrc = reinterpret_cast<const char*>(g_W) +
                               (size_t)nb * KC * 2 * BLK_BYTES;
            for (int i = 0; i < KC; ++i) {
                mbar_wait(empty0 + s * 8, ph);
                const uint32_t fb = full0 + s * 8;
                mbar_expect_tx(fb, STAGE_BYTES);
                const uint32_t stg = sbase + SMEM_STAGE0 + s * STAGE_BYTES;
                bulk_g2s(stg,             Asrc + (size_t)i * BLK_BYTES,     BLK_BYTES,     fb);
                bulk_g2s(stg + BLK_BYTES, Bsrc + (size_t)i * 2 * BLK_BYTES, 2 * BLK_BYTES, fb);
                if (++s == STAGES) { s = 0; ph ^= 1; }
            }
        }
    }

    // ==================== MMA issuer: warp 9, lane 0 ====================
    if (tid == 288) {
        int s = 0, ph = 0;
        int j = 0;
        for (int t = blockIdx.x; t < ntiles; t += gridDim.x, ++j) {
            const int buf = j & 1;
            const int u   = j >> 1;
            if (u > 0) mbar_wait(efree0 + buf * 8, (u - 1) & 1);
            tc_fence_after();
            const uint32_t dacc = tmem_base + buf * 256;
            for (int i = 0; i < KC; ++i) {
                mbar_wait(full0 + s * 8, ph);
                const uint32_t stg = sbase + SMEM_STAGE0 + s * STAGE_BYTES;
                uint64_t ad = make_desc(stg);
                uint64_t bd = make_desc(stg + BLK_BYTES);
#pragma unroll
                for (int ks = 0; ks < 4; ++ks) {
                    mma_f16_ss(dacc, ad + ks * 2, bd + ks * 2, IDESC,
                               (i > 0 || ks > 0) ? 1u : 0u);
                }
                tc_commit(empty0 + s * 8);
                if (++s == STAGES) { s = 0; ph ^= 1; }
            }
            tc_commit(done0 + buf * 8);
        }
    }

    // ==================== epilogue: warps 0-7 ====================
    if (wid < 8) {
        const int subp    = wid & 3;
        const int colhalf = wid >> 2;
        int j = 0;
        for (int t = blockIdx.x; t < ntiles; t += gridDim.x, ++j) {
            const int buf = j & 1;
            const int u   = j >> 1;
            mbar_wait(done0 + buf * 8, u & 1);
            tc_fence_after();

            int mb, nb;
            tile_coords(t, TILES_M, mb, nb);
            const int row = mb * 128 + subp * 32 + lane;
            float* orow = Out + (size_t)row * N + nb * 256 + colhalf * 128;
            const float* brow = bias + nb * 256 + colhalf * 128;
            const uint32_t tacc = tmem_base + buf * 256 + colhalf * 128;

#pragma unroll
            for (int cb = 0; cb < 4; ++cb) {
                uint32_t r32[32];
                ldtm_x32(r32, tacc + cb * 32);
                tc_wait_ld();
                float o[32];
#pragma unroll
                for (int q = 0; q < 8; ++q) {
                    const float4 bf = *reinterpret_cast<const float4*>(brow + cb * 32 + q * 4);
                    const float bfv[4] = {bf.x, bf.y, bf.z, bf.w};
#pragma unroll
                    for (int e = 0; e < 4; ++e) {
                        const int c = q * 4 + e;
                        __half h  = __float2half_rn(__uint_as_float(r32[c]));
                        __half hb = __float2half_rn(bfv[e]);
                        o[c] = __half2float(__hadd(h, hb));
                    }
                }
#pragma unroll
                for (int q = 0; q < 8; ++q) {
                    reinterpret_cast<float4*>(orow + cb * 32)[q] =
                        make_float4(o[4 * q], o[4 * q + 1], o[4 * q + 2], o[4 * q + 3]);
                }
            }
            tc_fence_before();
            if (lane == 0) mbar_arrive(efree0 + buf * 8);
        }
    }

    __syncthreads();
    if (wid == 8) tmem_dealloc(tmem_base, 512);

#else
    // =============== compile-only fallback (never selected on GB300) =======
    for (int t = blockIdx.x; t < ntiles; t += gridDim.x) {
        int mb, nb;
        tile_coords(t, TILES_M, mb, nb);
        for (int rr = tid; rr < 128; rr += THREADS) {
            const int m = mb * 128 + rr;
            for (int c = 0; c < 256; ++c) {
                const int n = nb * 256 + c;
                float acc = 0.0f;
                for (int k = 0; k < K; ++k) {
                    size_t ablk = (size_t)(m >> 7) * KC + (k >> 6);
                    const __half* ae = reinterpret_cast<const __half*>(
                        reinterpret_cast<const char*>(g_X) + ablk * BLK_BYTES +
                        swz128((uint32_t)((m & 127) * 128 + (k & 63) * 2)));
                    size_t bblk = ((size_t)(n >> 8) * KC + (k >> 6)) * 2 + ((n >> 7) & 1);
                    const __half* be = reinterpret_cast<const __half*>(
                        reinterpret_cast<const char*>(g_W) + bblk * BLK_BYTES +
                        swz128((uint32_t)((n & 127) * 128 + (k & 63) * 2)));
                    acc += __half2float(*ae) * __half2float(*be);
                }
                __half h = __hadd(__float2half_rn(acc), __float2half_rn(bias[n]));
                Out[(size_t)m * N + n] = __half2float(h);
            }
        }
    }
#endif
}

// ---------------------------------------------------------------------------
extern "C" void kernel_launch(void* const* d_in, const int* in_sizes, int n_in,
                              void* d_out, int out_size) {
    const float* x     = (const float*)d_in[0];
    const int*   wq    = (const int*)d_in[1];
    const float* scale = (const float*)d_in[2];
    const float* bias  = (const float*)d_in[3];
    float*       out   = (float*)d_out;

    const int O = in_sizes[3];                    // 4096
    const int K = (in_sizes[1] / O) * 2;          // 4096
    const int M = in_sizes[0] / K;                // 8192
    const int N = O;
    const int KC = K / KC_ELEMS;                  // 64
    const int ntiles = (M / 128) * (N / 256);     // 1024

    const int wblocks = (N / 128) * KC;           // 2048
    const int xblocks = (M / 128) * KC;           // 4096
    prepass_kernel<<<wblocks + xblocks, 256>>>(x, wq, scale, K, KC, wblocks);

    int nsm = 148;
    cudaDeviceGetAttribute(&nsm, cudaDevAttrMultiProcessorCount, 0);

    cudaFuncSetAttribute(gemm_kernel,
                         cudaFuncAttributeMaxDynamicSharedMemorySize,
                         SMEM_TOTAL_GEMM);
    gemm_kernel<<<nsm, THREADS, SMEM_TOTAL_GEMM>>>(bias, out, M, N, K, ntiles);
}